// round 2
// baseline (speedup 1.0000x reference)
#include <cuda_runtime.h>
#include <cuda_bf16.h>

// Problem dims (fixed for this problem)
#define PB 2048
#define PT 512
#define PI 64
#define PH 128
#define PKW 192          // I + H
#define TB 16            // batch rows per CTA
#define NTHR 128

// SMEM layout (floats)
#define WROW 132                   // padded row (k-major weight row: 128 floats + 4 pad, 16B aligned)
#define WBUF (PKW * WROW)          // 25344 floats per weight stage
#define W_OFF 0
#define X_OFF (2 * WBUF)           // 50688
#define XBUF (TB * PI)             // 1024
#define H_OFF (X_OFF + 2 * XBUF)   // 52736
#define B_OFF (H_OFF + TB * PH)    // 54784
#define I_OFF (B_OFF + 2 * PH)     // 55040 (int section)
#define SMEM_FLOATS (I_OFF + 32)
#define SMEM_BYTES (SMEM_FLOATS * 4)   // 220,288 B

// Pre-transposed weights: Wt[t][k][j], k in [0,192): k<64 -> W_xh, k>=64 -> W_hh
__device__ __align__(16) float g_Wt[(size_t)PT * PKW * PH];

// ---------------- helpers ----------------

__device__ __forceinline__ void cp_async16(void* smem_dst, const void* gsrc) {
    unsigned saddr = (unsigned)__cvta_generic_to_shared(smem_dst);
    asm volatile("cp.async.cg.shared.global [%0], [%1], 16;\n" :: "r"(saddr), "l"(gsrc) : "memory");
}
__device__ __forceinline__ void cp_commit() {
    asm volatile("cp.async.commit_group;\n" ::: "memory");
}
__device__ __forceinline__ void cp_wait_all() {
    asm volatile("cp.async.wait_group 0;\n" ::: "memory");
}

// packed fp32x2 FMA (Blackwell FFMA2)
__device__ __forceinline__ void ffma2(unsigned long long& d, unsigned long long a, unsigned long long b) {
    asm("fma.rn.f32x2 %0, %1, %2, %0;" : "+l"(d) : "l"(a), "l"(b));
}
__device__ __forceinline__ unsigned long long dup2(float v) {
    unsigned long long r;
    asm("mov.b64 %0, {%1, %1};" : "=l"(r) : "f"(v));
    return r;
}
__device__ __forceinline__ void unpack2(unsigned long long v, float& lo, float& hi) {
    asm("mov.b64 {%0, %1}, %2;" : "=f"(lo), "=f"(hi) : "l"(v));
}

__device__ __forceinline__ float fast_tanh(float v) {
    v = fminf(9.0f, fmaxf(-9.0f, v));
    float e = __expf(2.0f * v);
    return __fdividef(e - 1.0f, e + 1.0f);
}

// ---------------- pre-transpose kernels ----------------
// Wt[(t*192 + k)*128 + j] = (k<64) ? Wxh[(t*128+j)*64 + k] : Whh[(t*128+j)*128 + (k-64)]

__global__ void transpose_wxh(const float* __restrict__ Wxh) {
    __shared__ float tile[32][33];
    int t = blockIdx.z;
    int k0 = blockIdx.x * 32;   // k tiles: 2
    int j0 = blockIdx.y * 32;   // j tiles: 4
    for (int i = threadIdx.y; i < 32; i += 8)
        tile[i][threadIdx.x] = Wxh[((size_t)t * PH + (j0 + i)) * PI + k0 + threadIdx.x];
    __syncthreads();
    for (int i = threadIdx.y; i < 32; i += 8)
        g_Wt[((size_t)t * PKW + (k0 + i)) * PH + j0 + threadIdx.x] = tile[threadIdx.x][i];
}

__global__ void transpose_whh(const float* __restrict__ Whh) {
    __shared__ float tile[32][33];
    int t = blockIdx.z;
    int k0 = blockIdx.x * 32;   // k tiles: 4
    int j0 = blockIdx.y * 32;   // j tiles: 4
    for (int i = threadIdx.y; i < 32; i += 8)
        tile[i][threadIdx.x] = Whh[((size_t)t * PH + (j0 + i)) * PH + k0 + threadIdx.x];
    __syncthreads();
    for (int i = threadIdx.y; i < 32; i += 8)
        g_Wt[((size_t)t * PKW + (64 + k0 + i)) * PH + j0 + threadIdx.x] = tile[threadIdx.x][i];
}

// ---------------- main RNN kernel ----------------

__device__ __forceinline__ void load_stage(int t, int buf, int tid, int base,
                                           float* wS, float* xS, float* bS,
                                           const float* __restrict__ x,
                                           const float* __restrict__ bhh) {
    const float* wsrc = g_Wt + (size_t)t * PKW * PH;
    float* wdst = wS + buf * WBUF;
    // 192 rows x 128 floats = 6144 16B-chunks; 48 per thread
#pragma unroll
    for (int i = 0; i < 48; i++) {
        int c = tid + i * NTHR;
        int k = c >> 5, cc = c & 31;
        cp_async16(wdst + k * WROW + cc * 4, wsrc + k * PH + cc * 4);
    }
    // x tile: 16 rows x 64 floats = 256 chunks; 2 per thread
    float* xdst = xS + buf * XBUF;
#pragma unroll
    for (int i = 0; i < 2; i++) {
        int c = tid + i * NTHR;
        int b = c >> 4, cc = c & 15;
        cp_async16(xdst + b * PI + cc * 4,
                   x + ((size_t)(base + b) * PT + t) * PI + cc * 4);
    }
    // bias: 128 floats = 32 chunks
    if (tid < 32)
        cp_async16(bS + buf * PH + tid * 4, bhh + (size_t)t * PH + tid * 4);
}

__global__ void __launch_bounds__(NTHR)
rnn_kernel(const float* __restrict__ x, const int* __restrict__ lens,
           const float* __restrict__ bhh, const float* __restrict__ Wout,
           const float* __restrict__ bout, float* __restrict__ out) {
    extern __shared__ float sm[];
    float* wS = sm + W_OFF;
    float* xS = sm + X_OFF;
    float* hS = sm + H_OFF;
    float* bS = sm + B_OFF;
    int* iS = (int*)(sm + I_OFF);

    const int tid = threadIdx.x;
    const int jt = tid & 15;        // 16 j-thread groups
    const int btid = tid >> 4;      // 8 batch-thread groups
    const int b0 = 2 * btid;
    const int b1 = b0 + 1;
    const int base = blockIdx.x * TB;

    if (tid < TB) iS[tid] = lens[base + tid];
    __syncthreads();
    if (tid == 0) {
        int m = 0;
#pragma unroll
        for (int i = 0; i < TB; i++) m = max(m, iS[i]);
        iS[TB] = m;
    }
    // zero h
    for (int idx = tid; idx < TB * PH; idx += NTHR) hS[idx] = 0.0f;
    __syncthreads();

    const int tmax = iS[TB];
    const int len0 = iS[b0];
    const int len1 = iS[b1];

    if (tmax > 0) {
        load_stage(0, 0, tid, base, wS, xS, bS, x, bhh);
        cp_commit();
    }

    for (int t = 0; t < tmax; t++) {
        const int buf = t & 1;
        cp_wait_all();
        __syncthreads();   // stage t visible; everyone done reading buf^1 from iter t-1

        if (t + 1 < tmax)
            load_stage(t + 1, buf ^ 1, tid, base, wS, xS, bS, x, bhh);
        cp_commit();

        const float* wb = wS + buf * WBUF;
        const float* xb = xS + buf * XBUF;
        const float* bb = bS + buf * PH;

        unsigned long long acc[4][2];
#pragma unroll
        for (int p = 0; p < 4; p++) {
            unsigned long long bv = *(const unsigned long long*)(bb + 2 * jt + 32 * p);
            acc[p][0] = bv;
            acc[p][1] = bv;
        }

        // x phase: k in [0,64)
#pragma unroll 8
        for (int k = 0; k < PI; k++) {
            unsigned long long a0 = dup2(xb[b0 * PI + k]);
            unsigned long long a1 = dup2(xb[b1 * PI + k]);
            const float* wr = wb + k * WROW + 2 * jt;
#pragma unroll
            for (int p = 0; p < 4; p++) {
                unsigned long long w2 = *(const unsigned long long*)(wr + 32 * p);
                ffma2(acc[p][0], w2, a0);
                ffma2(acc[p][1], w2, a1);
            }
        }
        // h phase: k in [0,128)
#pragma unroll 8
        for (int k = 0; k < PH; k++) {
            unsigned long long a0 = dup2(hS[b0 * PH + k]);
            unsigned long long a1 = dup2(hS[b1 * PH + k]);
            const float* wr = wb + (PI + k) * WROW + 2 * jt;
#pragma unroll
            for (int p = 0; p < 4; p++) {
                unsigned long long w2 = *(const unsigned long long*)(wr + 32 * p);
                ffma2(acc[p][0], w2, a0);
                ffma2(acc[p][1], w2, a1);
            }
        }

        __syncthreads();   // all reads of hS done before anyone writes

#pragma unroll
        for (int p = 0; p < 4; p++) {
            const int j = 2 * jt + 32 * p;
            if (t < len0) {
                float lo, hi;
                unpack2(acc[p][0], lo, hi);
                float2 o = make_float2(fast_tanh(lo), fast_tanh(hi));
                *(float2*)(hS + b0 * PH + j) = o;
            }
            if (t < len1) {
                float lo, hi;
                unpack2(acc[p][1], lo, hi);
                float2 o = make_float2(fast_tanh(lo), fast_tanh(hi));
                *(float2*)(hS + b1 * PH + j) = o;
            }
        }
        // next iteration's top barrier orders these writes before reads
    }
    __syncthreads();

    // epilogue: out[b] = h[b] . Wout + bout
    {
        const int brow = tid >> 3;   // 16 rows
        const int g = tid & 7;
        float s = 0.0f;
#pragma unroll
        for (int j = g; j < PH; j += 8)
            s += hS[brow * PH + j] * __ldg(&Wout[j]);
        s += __shfl_xor_sync(0xffffffffu, s, 4);
        s += __shfl_xor_sync(0xffffffffu, s, 2);
        s += __shfl_xor_sync(0xffffffffu, s, 1);
        if (g == 0) out[base + brow] = s + __ldg(&bout[0]);
    }
}

// ---------------- launcher ----------------

extern "C" void kernel_launch(void* const* d_in, const int* in_sizes, int n_in,
                              void* d_out, int out_size) {
    const float* x    = (const float*)d_in[0];
    const int*   lens = (const int*)d_in[1];
    const float* Wxh  = (const float*)d_in[2];
    const float* Whh  = (const float*)d_in[3];
    const float* bhh  = (const float*)d_in[4];
    const float* Wout = (const float*)d_in[5];
    const float* bout = (const float*)d_in[6];
    float* out = (float*)d_out;

    cudaFuncSetAttribute(rnn_kernel, cudaFuncAttributeMaxDynamicSharedMemorySize, SMEM_BYTES);

    transpose_wxh<<<dim3(2, 4, PT), dim3(32, 8)>>>(Wxh);
    transpose_whh<<<dim3(4, 4, PT), dim3(32, 8)>>>(Whh);
    rnn_kernel<<<PB / TB, NTHR, SMEM_BYTES>>>(x, lens, bhh, Wout, bout, out);
}